// round 12
// baseline (speedup 1.0000x reference)
#include <cuda_runtime.h>
#include <cuda_bf16.h>
#include <cstdint>
#include <cstddef>

#define NB 16384
#define NV 1024
#define NH 256
#define KSTEPS 8
#define GW_ELEMS (NH*NV)          // 262144
#define OUT_VB_OFF GW_ELEMS
#define OUT_HB_OFF (GW_ELEMS+NV)
#define OUT_TOTAL (GW_ELEMS+NV+NH)
#define GW_SPLITK 8

typedef __nv_bfloat16 bf16;

// ---------------- static scratch ----------------
__device__ bf16  g_vbf[NB*NV];      // current visible state, bf16 (binary, exact)
__device__ bf16  g_batchbf[NB*NV];
__device__ bf16  g_hbf[NB*NH];      // hidden state, bf16 (binary, exact)
__device__ float g_preh[NB*NH];     // pre_k
__device__ float g_preh0[NB*NH];    // pre0
__device__ float g_invn[NB];
__device__ bf16  g_whi[NH*NV];
__device__ bf16  g_wlo[NH*NV];
__device__ bf16  g_akT_hi[NH*NB];
__device__ bf16  g_akT_lo[NH*NB];
__device__ bf16  g_na0T_hi[NH*NB];
__device__ bf16  g_na0T_lo[NH*NB];
__device__ bf16  g_vkT[NV*NB];
__device__ bf16  g_v0T[NV*NB];
__device__ float g_gw_part[GW_SPLITK*GW_ELEMS];
__device__ float g_vb_part[32*NV];
__device__ float g_hb_part[32*NH];

// ---------------- threefry2x32 (JAX partitionable) ----------------
__host__ __device__ __forceinline__ void threefry2x32(
    uint32_t k0, uint32_t k1, uint32_t c0, uint32_t c1,
    uint32_t& o0, uint32_t& o1)
{
    uint32_t k2 = k0 ^ k1 ^ 0x1BD11BDAu;
    uint32_t x0 = c0 + k0, x1 = c1 + k1;
#define TF_R(r) { x0 += x1; x1 = (x1 << (r)) | (x1 >> (32 - (r))); x1 ^= x0; }
    TF_R(13) TF_R(15) TF_R(26) TF_R(6)
    x0 += k1; x1 += k2 + 1u;
    TF_R(17) TF_R(29) TF_R(16) TF_R(24)
    x0 += k2; x1 += k0 + 2u;
    TF_R(13) TF_R(15) TF_R(26) TF_R(6)
    x0 += k0; x1 += k1 + 3u;
    TF_R(17) TF_R(29) TF_R(16) TF_R(24)
    x0 += k1; x1 += k2 + 4u;
    TF_R(13) TF_R(15) TF_R(26) TF_R(6)
    x0 += k2; x1 += k0 + 5u;
#undef TF_R
    o0 = x0; o1 = x1;
}

__device__ __forceinline__ float tf_uniform(uint32_t bits) {
    return __uint_as_float((bits >> 9) | 0x3f800000u) - 1.0f;
}
__device__ __forceinline__ float sigmoid_f(float x) {
    return 1.0f / (1.0f + expf(-x));
}
__device__ __forceinline__ float tf_sample(uint32_t k0, uint32_t k1, uint32_t e, float pre) {
    uint32_t o0, o1;
    threefry2x32(k0, k1, 0u, e, o0, o1);
    return (tf_uniform(o0 ^ o1) < sigmoid_f(pre)) ? 1.0f : 0.0f;
}

// ---------------- cp.async / ldmatrix / mma helpers ----------------
__device__ __forceinline__ void cpa16(void* s, const void* g) {
    uint32_t sa = (uint32_t)__cvta_generic_to_shared(s);
    asm volatile("cp.async.ca.shared.global [%0], [%1], 16;\n" :: "r"(sa), "l"(g));
}
__device__ __forceinline__ void cpa_commit() {
    asm volatile("cp.async.commit_group;\n" ::);
}
__device__ __forceinline__ void cpa_wait1() {
    asm volatile("cp.async.wait_group 1;\n" ::);
}
__device__ __forceinline__ void cpa_wait0() {
    asm volatile("cp.async.wait_group 0;\n" ::);
}
__device__ __forceinline__ void ldsm4(uint32_t& r0, uint32_t& r1, uint32_t& r2, uint32_t& r3,
                                      uint32_t addr) {
    asm volatile("ldmatrix.sync.aligned.m8n8.x4.shared.b16 {%0,%1,%2,%3}, [%4];\n"
                 : "=r"(r0), "=r"(r1), "=r"(r2), "=r"(r3) : "r"(addr));
}
__device__ __forceinline__ void mma16816(float* c, const uint32_t* a, const uint32_t* b) {
    asm volatile(
        "mma.sync.aligned.m16n8k16.row.col.f32.bf16.bf16.f32 "
        "{%0,%1,%2,%3}, {%4,%5,%6,%7}, {%8,%9}, {%0,%1,%2,%3};\n"
        : "+f"(c[0]), "+f"(c[1]), "+f"(c[2]), "+f"(c[3])
        : "r"(a[0]), "r"(a[1]), "r"(a[2]), "r"(a[3]), "r"(b[0]), "r"(b[1]));
}

// SMEM tile row stride: 32 bf16 payload, stride 40 bf16 (80B: 16B-aligned, LDSM conflict-free)
#define TSTRIDE 40

// ---- gw (128x128) stage layout ----
#define STAGE_ELE (128*TSTRIDE)
#define STAGE_BYTES (2*STAGE_ELE*2)        // 20480
#define GW_SMEM_BYTES (3*STAGE_BYTES)      // 61440

// ---- fgemm (256x128) stage layout: [A 256*40 | B 128*40] ----
#define FG_A_ELE (256*TSTRIDE)
#define FG_B_ELE (128*TSTRIDE)
#define FG_STAGE_ELE (FG_A_ELE + FG_B_ELE)
#define FG_STAGE_BYTES (FG_STAGE_ELE*2)    // 30720
#define FG_SMEM_BYTES (3*FG_STAGE_BYTES)   // 92160

// 128-row tile loader, 256 threads (2 chunks each)
__device__ __forceinline__ void load_tile128_t256(bf16* s, const bf16* g, size_t ldg, int tid) {
#pragma unroll
    for (int i = 0; i < 2; i++) {
        int c = tid + 256*i;
        int row = c >> 2, w = c & 3;
        cpa16(s + row*TSTRIDE + w*8, g + (size_t)row*ldg + w*8);
    }
}
// 256-row tile loader, 512 threads (2 chunks each)
__device__ __forceinline__ void load_tile256_t512(bf16* s, const bf16* g, size_t ldg, int tid) {
#pragma unroll
    for (int i = 0; i < 2; i++) {
        int c = tid + 512*i;
        int row = c >> 2, w = c & 3;
        cpa16(s + row*TSTRIDE + w*8, g + (size_t)row*ldg + w*8);
    }
}
// 128-row tile loader, 512 threads (1 chunk each)
__device__ __forceinline__ void load_tile128_t512(bf16* s, const bf16* g, size_t ldg, int tid) {
    int row = tid >> 2, w = tid & 3;
    cpa16(s + row*TSTRIDE + w*8, g + (size_t)row*ldg + w*8);
}

// ldmatrix-based compute of one (64x128)x32 warp tile at row offset arow, col offset bcol.
// kk/mi/ni order fixed -> per-output accumulation bit-identical across layouts.
__device__ __forceinline__ void mma_tile_ldsm(uint32_t aBase, uint32_t bBase,
                                              int arow, int bcol, int lane,
                                              float acc[4][4][4]) {
    int lr = lane & 15;
    int kadd = (lane >> 4) * 8;
#pragma unroll
    for (int kk = 0; kk < 32; kk += 16) {
        uint32_t a[4][4], b[4][2];
#pragma unroll
        for (int mi = 0; mi < 4; mi++) {
            uint32_t addr = aBase + (uint32_t)(((arow + mi*16 + lr)*TSTRIDE + kk + kadd) * 2);
            ldsm4(a[mi][0], a[mi][1], a[mi][2], a[mi][3], addr);
        }
#pragma unroll
        for (int np = 0; np < 2; np++) {
            uint32_t addr = bBase + (uint32_t)(((bcol + np*16 + lr)*TSTRIDE + kk + kadd) * 2);
            uint32_t r0, r1, r2, r3;
            ldsm4(r0, r1, r2, r3, addr);
            b[np*2][0]   = r0;
            b[np*2+1][0] = r1;
            b[np*2][1]   = r2;
            b[np*2+1][1] = r3;
        }
#pragma unroll
        for (int mi = 0; mi < 4; mi++)
#pragma unroll
            for (int ni = 0; ni < 4; ni++)
                mma16816(acc[mi][ni], a[mi], b[ni]);
    }
}

// ---------------- forward GEMM: pre[M,NH] = v[M,NV] @ (Whi|Wlo)^T + hb ----------------
// BM=256, BN=128, 512 threads (16 warps), grid (64,2)=128 blocks (1 wave)
template<bool SAMPLE>
__global__ __launch_bounds__(512) void fgemm_kernel(
    const bf16* __restrict__ A, const bf16* __restrict__ Whi,
    const bf16* __restrict__ Wlo, const float* __restrict__ bias,
    float* __restrict__ C, bf16* __restrict__ H,
    uint32_t k0, uint32_t k1)
{
    extern __shared__ __align__(16) bf16 dsm[];
    int m0 = blockIdx.x * 256;
    int n0 = blockIdx.y * 128;
    int tid = threadIdx.x;
    int warp = tid >> 5, lane = tid & 31;
    int arow = (warp & 3) * 64;
    int bcol = (warp >> 2) * 32;
    uint32_t sbase = (uint32_t)__cvta_generic_to_shared(dsm);

    float acc[4][4][4];
#pragma unroll
    for (int mi = 0; mi < 4; mi++)
#pragma unroll
        for (int ni = 0; ni < 4; ni++)
#pragma unroll
            for (int j = 0; j < 4; j++) acc[mi][ni][j] = 0.0f;

    const int NIT = 64;
#pragma unroll
    for (int jt = 0; jt < 2; jt++) {
        bf16* sA = dsm + jt*FG_STAGE_ELE;
        int k = (jt & 31) * 32;
        load_tile256_t512(sA, A + (size_t)m0*NV + k, NV, tid);
        load_tile128_t512(sA + FG_A_ELE, Whi + (size_t)n0*NV + k, NV, tid);
        cpa_commit();
    }

    for (int it = 0; it < NIT; it++) {
        if (it == NIT-1) cpa_wait0(); else cpa_wait1();
        __syncthreads();
        if (it + 2 < NIT) {
            int jt = it + 2;
            int st = jt % 3;
            int k = (jt & 31) * 32;
            const bf16* Bp = (jt < 32) ? Whi : Wlo;
            bf16* sA = dsm + st*FG_STAGE_ELE;
            load_tile256_t512(sA, A + (size_t)m0*NV + k, NV, tid);
            load_tile128_t512(sA + FG_A_ELE, Bp + (size_t)n0*NV + k, NV, tid);
            cpa_commit();
        }
        int st = it % 3;
        uint32_t aB = sbase + st*FG_STAGE_BYTES;
        mma_tile_ldsm(aB, aB + FG_A_ELE*2, arow, bcol, lane, acc);
    }

#pragma unroll
    for (int mi = 0; mi < 4; mi++) {
        int m = m0 + arow + mi*16 + (lane>>2);
#pragma unroll
        for (int ni = 0; ni < 4; ni++) {
            int n = n0 + bcol + ni*8 + 2*(lane&3);
            float2 b2 = *(const float2*)&bias[n];
            float p00 = acc[mi][ni][0] + b2.x;
            float p01 = acc[mi][ni][1] + b2.y;
            float p10 = acc[mi][ni][2] + b2.x;
            float p11 = acc[mi][ni][3] + b2.y;
            if (SAMPLE) {
                uint32_t e0 = (uint32_t)(m*NH + n);
                uint32_t e1 = (uint32_t)((m+8)*NH + n);
                __nv_bfloat162 h0, h1;
                h0.x = __float2bfloat16(tf_sample(k0, k1, e0,     p00));
                h0.y = __float2bfloat16(tf_sample(k0, k1, e0 + 1, p01));
                h1.x = __float2bfloat16(tf_sample(k0, k1, e1,     p10));
                h1.y = __float2bfloat16(tf_sample(k0, k1, e1 + 1, p11));
                *(__nv_bfloat162*)&H[(size_t)m*NH + n] = h0;
                *(__nv_bfloat162*)&H[(size_t)(m+8)*NH + n] = h1;
            } else {
                float2 r0 = { p00, p01 };
                float2 r1 = { p10, p11 };
                *(float2*)&C[(size_t)m*NH + n] = r0;
                *(float2*)&C[(size_t)(m+8)*NH + n] = r1;
            }
        }
    }
}

// ---------------- gw GEMM (split-K=8 -> 2x8x8 = 128 blocks = 1 wave) ----------------
__global__ __launch_bounds__(256) void gw_mma_kernel(
    const bf16* __restrict__ A0p, const bf16* __restrict__ A1p,
    const bf16* __restrict__ A2p, const bf16* __restrict__ A3p,
    const bf16* __restrict__ Bk, const bf16* __restrict__ B0,
    float* __restrict__ part)
{
    extern __shared__ __align__(16) bf16 dsm[];
    int m0 = blockIdx.x * 128;
    int n0 = blockIdx.y * 128;
    int ks = blockIdx.z;
    size_t kbase = (size_t)ks * (NB / GW_SPLITK);   // chunk 2048
    int tid = threadIdx.x;
    int warp = tid >> 5, lane = tid & 31;
    int arow = (warp & 1) * 64;
    int bcol = (warp >> 1) * 32;
    uint32_t sbase = (uint32_t)__cvta_generic_to_shared(dsm);

    const bf16* Ap[4] = { A0p, A1p, A2p, A3p };
    const bf16* Bp[4] = { Bk, Bk, B0, B0 };

    float acc[4][4][4];
#pragma unroll
    for (int mi = 0; mi < 4; mi++)
#pragma unroll
        for (int ni = 0; ni < 4; ni++)
#pragma unroll
            for (int j = 0; j < 4; j++) acc[mi][ni][j] = 0.0f;

    const int NIT = 256;   // 4 passes x 64 iters (chunk 2048 / 32)
#pragma unroll
    for (int jt = 0; jt < 2; jt++) {
        bf16* sA = dsm + jt*(2*STAGE_ELE);
        size_t k = kbase + (size_t)(jt & 63) * 32;
        load_tile128_t256(sA, Ap[0] + (size_t)m0*NB + k, NB, tid);
        load_tile128_t256(sA + STAGE_ELE, Bp[0] + (size_t)n0*NB + k, NB, tid);
        cpa_commit();
    }

    for (int it = 0; it < NIT; it++) {
        if (it == NIT-1) cpa_wait0(); else cpa_wait1();
        __syncthreads();
        if (it + 2 < NIT) {
            int jt = it + 2;
            int st = jt % 3;
            int p = jt >> 6;
            size_t k = kbase + (size_t)(jt & 63) * 32;
            bf16* sA = dsm + st*(2*STAGE_ELE);
            load_tile128_t256(sA, Ap[p] + (size_t)m0*NB + k, NB, tid);
            load_tile128_t256(sA + STAGE_ELE, Bp[p] + (size_t)n0*NB + k, NB, tid);
            cpa_commit();
        }
        int st = it % 3;
        uint32_t aB = sbase + st*STAGE_BYTES;
        mma_tile_ldsm(aB, aB + STAGE_ELE*2, arow, bcol, lane, acc);
    }

#pragma unroll
    for (int mi = 0; mi < 4; mi++) {
        int m = m0 + arow + mi*16 + (lane>>2);
#pragma unroll
        for (int ni = 0; ni < 4; ni++) {
            int n = n0 + bcol + ni*8 + 2*(lane&3);
            float2 r0 = { acc[mi][ni][0], acc[mi][ni][1] };
            float2 r1 = { acc[mi][ni][2], acc[mi][ni][3] };
            *(float2*)&part[(size_t)ks*GW_ELEMS + (size_t)m*NV + n] = r0;
            *(float2*)&part[(size_t)ks*GW_ELEMS + (size_t)(m+8)*NV + n] = r1;
        }
    }
}

// ---------------- fused sparse h @ W + vb -> sample visible -> bf16 v ----------------
// 2 warps per sample: warp half 0 -> cols [0,512), half 1 -> [512,1024)
__global__ __launch_bounds__(256) void spmm_sample_kernel(
    const bf16* __restrict__ h, const float* __restrict__ Wm,
    const float* __restrict__ vb, bf16* __restrict__ vout,
    uint32_t k0, uint32_t k1)
{
    int tid = threadIdx.x;
    int lane = tid & 31;
    int half = (tid >> 5) & 1;
    int sample = blockIdx.x * 4 + (tid >> 6);
    int cbase = half * 512 + lane;

    const bf16* hr = h + (size_t)sample * NH;
    float acc[16];
#pragma unroll
    for (int t = 0; t < 16; t++) acc[t] = vb[cbase + t*32];
#pragma unroll
    for (int g = 0; g < 8; g++) {
        float hv = __bfloat162float(hr[g*32 + lane]);
        unsigned mask = __ballot_sync(0xffffffffu, hv != 0.0f);
        while (mask) {
            int bit = __ffs(mask) - 1; mask &= mask - 1;
            const float* wr = Wm + (size_t)(g*32 + bit) * NV + cbase;
#pragma unroll
            for (int t = 0; t < 16; t++) acc[t] += wr[t*32];
        }
    }
    uint32_t ebase = (uint32_t)sample * NV + cbase;
    bf16* outp = vout + (size_t)sample * NV + cbase;
#pragma unroll
    for (int t = 0; t < 16; t++) {
        float s = tf_sample(k0, k1, ebase + t*32, acc[t]);
        outp[t*32] = __float2bfloat16(s);
    }
}

// ---------------- inv_norm ----------------
__global__ __launch_bounds__(256) void invn_kernel(
    const float* __restrict__ prek, const bf16* __restrict__ vk,
    const float* __restrict__ vb, float* __restrict__ invn)
{
    int warp = (blockIdx.x * blockDim.x + threadIdx.x) >> 5;
    int lane = threadIdx.x & 31;
    if (warp >= NB) return;
    float s = 0.0f;
    const float* pr = prek + (size_t)warp * NH;
#pragma unroll
    for (int t = 0; t < 8; t++) {
        float x = pr[t*32 + lane];
        s += fmaxf(x, 0.0f) + log1pf(expf(-fabsf(x)));
    }
    const bf16* vr = vk + (size_t)warp * NV;
#pragma unroll
    for (int t = 0; t < 32; t++)
        s = fmaf(__bfloat162float(vr[t*32 + lane]), vb[t*32 + lane], s);
#pragma unroll
    for (int o = 16; o > 0; o >>= 1) s += __shfl_xor_sync(0xffffffffu, s, o);
    if (lane == 0) invn[warp] = expf(-s) * (1.0f / (float)NB);
}

// ---------------- fused: a = sign*invn*sigmoid(pre), transpose + hi/lo split ----------
__global__ __launch_bounds__(256) void trans_a_kernel(
    const float* __restrict__ src, const float* __restrict__ invn, float sign,
    bf16* __restrict__ dhi, bf16* __restrict__ dlo)
{
    __shared__ float t[32][33];
    int b0 = blockIdx.x * 32, h0 = blockIdx.y * 32;
    int tid = threadIdx.x;
#pragma unroll
    for (int i = 0; i < 4; i++) {
        int idx = tid + 256*i; int bl = idx >> 5, hl = idx & 31;
        float pre = src[(size_t)(b0+bl)*NH + h0 + hl];
        t[hl][bl] = invn[b0+bl] * sigmoid_f(pre);
    }
    __syncthreads();
#pragma unroll
    for (int i = 0; i < 4; i++) {
        int idx = tid + 256*i; int hl = idx >> 5, bl = idx & 31;
        float v = sign * t[hl][bl];
        bf16 hi = __float2bfloat16(v);
        float lo = v - __bfloat162float(hi);
        size_t o = (size_t)(h0+hl)*NB + b0 + bl;
        dhi[o] = hi; dlo[o] = __float2bfloat16(lo);
    }
}

// bf16 [NB,NV] -> bf16 [NV,NB] transpose
__global__ __launch_bounds__(256) void trans_vbf_kernel(
    const bf16* __restrict__ src, bf16* __restrict__ dst)
{
    __shared__ uint16_t t[32][34];
    int b0 = blockIdx.x * 32, v0 = blockIdx.y * 32;
    int tid = threadIdx.x;
#pragma unroll
    for (int i = 0; i < 4; i++) {
        int idx = tid + 256*i; int bl = idx >> 5, vl = idx & 31;
        t[vl][bl] = ((const uint16_t*)src)[(size_t)(b0+bl)*NV + v0 + vl];
    }
    __syncthreads();
#pragma unroll
    for (int i = 0; i < 4; i++) {
        int idx = tid + 256*i; int vl = idx >> 5, bl = idx & 31;
        ((uint16_t*)dst)[(size_t)(v0+vl)*NB + b0 + bl] = t[vl][bl];
    }
}

// ---------------- W split, batch convert ----------------
__global__ __launch_bounds__(256) void wsplit_kernel(
    const float* __restrict__ W, bf16* __restrict__ whi, bf16* __restrict__ wlo)
{
    int i = blockIdx.x * 256 + threadIdx.x;
    if (i >= NH*NV) return;
    float w = W[i];
    bf16 hi = __float2bfloat16(w);
    whi[i] = hi;
    wlo[i] = __float2bfloat16(w - __bfloat162float(hi));
}

__global__ __launch_bounds__(256) void bconv_kernel(
    const float* __restrict__ src, bf16* __restrict__ dst, int n)
{
    int i = blockIdx.x * 256 + threadIdx.x;
    if (i < n) dst[i] = __float2bfloat16(src[i]);
}

// ---------------- g_vb / g_hb partials ----------------
__global__ __launch_bounds__(256) void vb_part_kernel(
    const bf16* __restrict__ vk, const bf16* __restrict__ v0,
    const float* __restrict__ invn, float* __restrict__ part)
{
    int v = blockIdx.x * 256 + threadIdx.x;
    int b0 = blockIdx.y * (NB / 32);
    float s = 0.0f;
    for (int b = b0; b < b0 + NB/32; b++) {
        float d = __bfloat162float(vk[(size_t)b*NV + v])
                - __bfloat162float(v0[(size_t)b*NV + v]);
        s = fmaf(invn[b], d, s);
    }
    part[blockIdx.y * NV + v] = s;
}

// hb partials from transposed hi/lo arrays
__global__ __launch_bounds__(256) void hb_part_kernel(
    const bf16* __restrict__ akhi, const bf16* __restrict__ aklo,
    const bf16* __restrict__ nahi, const bf16* __restrict__ nalo,
    float* __restrict__ part)
{
    int w = threadIdx.x >> 5, lane = threadIdx.x & 31;
    int h = blockIdx.x * 8 + w;
    int b0 = blockIdx.y * 512;
    size_t base = (size_t)h*NB + b0 + lane;
    float s = 0.0f;
#pragma unroll
    for (int j = 0; j < 16; j++) {
        size_t o = base + j*32;
        s += __bfloat162float(akhi[o]) + __bfloat162float(aklo[o])
           + __bfloat162float(nahi[o]) + __bfloat162float(nalo[o]);
    }
#pragma unroll
    for (int o = 16; o > 0; o >>= 1) s += __shfl_xor_sync(0xffffffffu, s, o);
    if (lane == 0) part[blockIdx.y * NH + h] = s;
}

// ---------------- finalize ----------------
__global__ __launch_bounds__(256) void finalize_kernel(
    const float* __restrict__ gw_part, const float* __restrict__ vb_part,
    const float* __restrict__ hb_part, float* __restrict__ out)
{
    int i = blockIdx.x * 256 + threadIdx.x;
    if (i < GW_ELEMS) {
        float s = 0.0f;
#pragma unroll
        for (int k = 0; k < GW_SPLITK; k++) s += gw_part[(size_t)k*GW_ELEMS + i];
        out[i] = s;
    } else if (i < OUT_HB_OFF) {
        int v = i - OUT_VB_OFF;
        float s = 0.0f;
#pragma unroll
        for (int k = 0; k < 32; k++) s += vb_part[k*NV + v];
        out[i] = s;
    } else if (i < OUT_TOTAL) {
        int h = i - OUT_HB_OFF;
        float s = 0.0f;
#pragma unroll
        for (int k = 0; k < 32; k++) s += hb_part[k*NH + h];
        out[i] = s;
    }
}

// ---------------- launch ----------------
extern "C" void kernel_launch(void* const* d_in, const int* in_sizes, int n_in,
                              void* d_out, int out_size)
{
    (void)in_sizes; (void)n_in; (void)out_size;
    const float* batch = (const float*)d_in[0];
    const float* W     = (const float*)d_in[1];
    const float* vb    = (const float*)d_in[2];
    const float* hb    = (const float*)d_in[3];
    float* out = (float*)d_out;

    float *ppreh, *ppreh0, *pinvn, *pgw, *pvbp, *phbp;
    bf16 *pvbf, *pbbf, *phbf, *pwhi, *pwlo, *pakhi, *paklo, *pna0hi, *pna0lo, *pvkT, *pv0T;
    cudaGetSymbolAddress((void**)&pvbf,   g_vbf);
    cudaGetSymbolAddress((void**)&pbbf,   g_batchbf);
    cudaGetSymbolAddress((void**)&phbf,   g_hbf);
    cudaGetSymbolAddress((void**)&ppreh,  g_preh);
    cudaGetSymbolAddress((void**)&ppreh0, g_preh0);
    cudaGetSymbolAddress((void**)&pinvn,  g_invn);
    cudaGetSymbolAddress((void**)&pwhi,   g_whi);
    cudaGetSymbolAddress((void**)&pwlo,   g_wlo);
    cudaGetSymbolAddress((void**)&pakhi,  g_akT_hi);
    cudaGetSymbolAddress((void**)&paklo,  g_akT_lo);
    cudaGetSymbolAddress((void**)&pna0hi, g_na0T_hi);
    cudaGetSymbolAddress((void**)&pna0lo, g_na0T_lo);
    cudaGetSymbolAddress((void**)&pvkT,   g_vkT);
    cudaGetSymbolAddress((void**)&pv0T,   g_v0T);
    cudaGetSymbolAddress((void**)&pgw,    g_gw_part);
    cudaGetSymbolAddress((void**)&pvbp,   g_vb_part);
    cudaGetSymbolAddress((void**)&phbp,   g_hb_part);

    cudaFuncSetAttribute(fgemm_kernel<true>,
        cudaFuncAttributeMaxDynamicSharedMemorySize, FG_SMEM_BYTES);
    cudaFuncSetAttribute(fgemm_kernel<false>,
        cudaFuncAttributeMaxDynamicSharedMemorySize, FG_SMEM_BYTES);
    cudaFuncSetAttribute(gw_mma_kernel,
        cudaFuncAttributeMaxDynamicSharedMemorySize, GW_SMEM_BYTES);

    // JAX partitionable split: key_m = threefry2x32((0,42), 0, m)
    uint32_t keys[16][2];
    for (int m = 0; m < 16; m++) {
        uint32_t o0, o1;
        threefry2x32(0u, 42u, 0u, (uint32_t)m, o0, o1);
        keys[m][0] = o0; keys[m][1] = o1;
    }

    const int totV = NB*NV;
    dim3 fgrid(NB/256, NH/128);   // (64, 2) = 128 blocks

    wsplit_kernel<<<(NH*NV + 255)/256, 256>>>(W, pwhi, pwlo);
    bconv_kernel<<<(totV + 255)/256, 256>>>(batch, pbbf, totV);

    for (int s = 0; s < KSTEPS; s++) {
        const bf16* Ain = (s == 0) ? pbbf : pvbf;
        fgemm_kernel<true><<<fgrid, 512, FG_SMEM_BYTES>>>(Ain, pwhi, pwlo, hb,
                                           (float*)nullptr, phbf,
                                           keys[2*s][0], keys[2*s][1]);
        spmm_sample_kernel<<<NB/4, 256>>>(phbf, W, vb, pvbf,
                                          keys[2*s+1][0], keys[2*s+1][1]);
    }

    fgemm_kernel<false><<<fgrid, 512, FG_SMEM_BYTES>>>(pvbf, pwhi, pwlo, hb,
                                        ppreh,  (bf16*)nullptr, 0u, 0u);
    fgemm_kernel<false><<<fgrid, 512, FG_SMEM_BYTES>>>(pbbf, pwhi, pwlo, hb,
                                        ppreh0, (bf16*)nullptr, 0u, 0u);
    invn_kernel<<<NB/8, 256>>>(ppreh, pvbf, vb, pinvn);

    trans_a_kernel<<<dim3(NB/32, NH/32), 256>>>(ppreh,  pinvn,  1.0f, pakhi, paklo);
    trans_a_kernel<<<dim3(NB/32, NH/32), 256>>>(ppreh0, pinvn, -1.0f, pna0hi, pna0lo);
    trans_vbf_kernel<<<dim3(NB/32, NV/32), 256>>>(pvbf, pvkT);
    trans_vbf_kernel<<<dim3(NB/32, NV/32), 256>>>(pbbf, pv0T);

    gw_mma_kernel<<<dim3(NH/128, NV/128, GW_SPLITK), 256, GW_SMEM_BYTES>>>(
        pakhi, paklo, pna0hi, pna0lo, pvkT, pv0T, pgw);

    vb_part_kernel<<<dim3(NV/256, 32), 256>>>(pvbf, pbbf, pinvn, pvbp);
    hb_part_kernel<<<dim3(NH/8, 32), 256>>>(pakhi, paklo, pna0hi, pna0lo, phbp);
    finalize_kernel<<<(OUT_TOTAL + 255)/256, 256>>>(pgw, pvbp, phbp, out);
}

// round 14
// speedup vs baseline: 1.0483x; 1.0483x over previous
#include <cuda_runtime.h>
#include <cuda_bf16.h>
#include <cstdint>
#include <cstddef>

#define NB 16384
#define NV 1024
#define NH 256
#define KSTEPS 8
#define GW_ELEMS (NH*NV)          // 262144
#define OUT_VB_OFF GW_ELEMS
#define OUT_HB_OFF (GW_ELEMS+NV)
#define OUT_TOTAL (GW_ELEMS+NV+NH)
#define GW_SPLITK 16

typedef __nv_bfloat16 bf16;

// ---------------- static scratch ----------------
__device__ bf16  g_vbf[NB*NV];      // current visible state, bf16 (binary, exact)
__device__ bf16  g_batchbf[NB*NV];
__device__ bf16  g_hbf[NB*NH];      // hidden state, bf16 (binary, exact)
__device__ float g_preh[NB*NH];     // pre_k
__device__ float g_preh0[NB*NH];    // pre0
__device__ float g_invn[NB];
__device__ bf16  g_whi[NH*NV];
__device__ bf16  g_wlo[NH*NV];
__device__ bf16  g_akT_hi[NH*NB];
__device__ bf16  g_akT_lo[NH*NB];
__device__ bf16  g_na0T_hi[NH*NB];
__device__ bf16  g_na0T_lo[NH*NB];
__device__ bf16  g_vkT[NV*NB];
__device__ bf16  g_v0T[NV*NB];
__device__ float g_gw_part[GW_SPLITK*GW_ELEMS];
__device__ float g_vb_part[32*NV];
__device__ float g_hb_part[32*NH];

// ---------------- threefry2x32 (JAX partitionable) ----------------
__host__ __device__ __forceinline__ void threefry2x32(
    uint32_t k0, uint32_t k1, uint32_t c0, uint32_t c1,
    uint32_t& o0, uint32_t& o1)
{
    uint32_t k2 = k0 ^ k1 ^ 0x1BD11BDAu;
    uint32_t x0 = c0 + k0, x1 = c1 + k1;
#define TF_R(r) { x0 += x1; x1 = (x1 << (r)) | (x1 >> (32 - (r))); x1 ^= x0; }
    TF_R(13) TF_R(15) TF_R(26) TF_R(6)
    x0 += k1; x1 += k2 + 1u;
    TF_R(17) TF_R(29) TF_R(16) TF_R(24)
    x0 += k2; x1 += k0 + 2u;
    TF_R(13) TF_R(15) TF_R(26) TF_R(6)
    x0 += k0; x1 += k1 + 3u;
    TF_R(17) TF_R(29) TF_R(16) TF_R(24)
    x0 += k1; x1 += k2 + 4u;
    TF_R(13) TF_R(15) TF_R(26) TF_R(6)
    x0 += k2; x1 += k0 + 5u;
#undef TF_R
    o0 = x0; o1 = x1;
}

__device__ __forceinline__ float tf_uniform(uint32_t bits) {
    return __uint_as_float((bits >> 9) | 0x3f800000u) - 1.0f;
}
__device__ __forceinline__ float sigmoid_f(float x) {
    return 1.0f / (1.0f + expf(-x));
}
__device__ __forceinline__ float tf_sample(uint32_t k0, uint32_t k1, uint32_t e, float pre) {
    uint32_t o0, o1;
    threefry2x32(k0, k1, 0u, e, o0, o1);
    return (tf_uniform(o0 ^ o1) < sigmoid_f(pre)) ? 1.0f : 0.0f;
}

// ---------------- cp.async / ldmatrix / mma helpers ----------------
__device__ __forceinline__ void cpa16(void* s, const void* g) {
    uint32_t sa = (uint32_t)__cvta_generic_to_shared(s);
    asm volatile("cp.async.ca.shared.global [%0], [%1], 16;\n" :: "r"(sa), "l"(g));
}
__device__ __forceinline__ void cpa_commit() {
    asm volatile("cp.async.commit_group;\n" ::);
}
__device__ __forceinline__ void cpa_wait2() {
    asm volatile("cp.async.wait_group 2;\n" ::);
}
__device__ __forceinline__ void cpa_wait1() {
    asm volatile("cp.async.wait_group 1;\n" ::);
}
__device__ __forceinline__ void cpa_wait0() {
    asm volatile("cp.async.wait_group 0;\n" ::);
}
__device__ __forceinline__ void ldsm4(uint32_t& r0, uint32_t& r1, uint32_t& r2, uint32_t& r3,
                                      uint32_t addr) {
    asm volatile("ldmatrix.sync.aligned.m8n8.x4.shared.b16 {%0,%1,%2,%3}, [%4];\n"
                 : "=r"(r0), "=r"(r1), "=r"(r2), "=r"(r3) : "r"(addr));
}
__device__ __forceinline__ void mma16816(float* c, const uint32_t* a, const uint32_t* b) {
    asm volatile(
        "mma.sync.aligned.m16n8k16.row.col.f32.bf16.bf16.f32 "
        "{%0,%1,%2,%3}, {%4,%5,%6,%7}, {%8,%9}, {%0,%1,%2,%3};\n"
        : "+f"(c[0]), "+f"(c[1]), "+f"(c[2]), "+f"(c[3])
        : "r"(a[0]), "r"(a[1]), "r"(a[2]), "r"(a[3]), "r"(b[0]), "r"(b[1]));
}

// SMEM tile row stride: 32 bf16 payload, stride 40 bf16 (80B: 16B-aligned, LDSM conflict-free)
#define TSTRIDE 40

// stage = [A 128x40 | B 128x40] bf16
#define STAGE_ELE (128*TSTRIDE)
#define STAGE_BYTES (2*STAGE_ELE*2)        // 20480
#define GW_SMEM_BYTES (3*STAGE_BYTES)      // 61440 (3-stage)
#define FG_SMEM_BYTES (4*STAGE_BYTES)      // 81920 (4-stage)

// 128-row tile loader, 256 threads (2 chunks each)
__device__ __forceinline__ void load_tile128_t256(bf16* s, const bf16* g, size_t ldg, int tid) {
#pragma unroll
    for (int i = 0; i < 2; i++) {
        int c = tid + 256*i;
        int row = c >> 2, w = c & 3;
        cpa16(s + row*TSTRIDE + w*8, g + (size_t)row*ldg + w*8);
    }
}

// ldmatrix-based compute of one (64x128)x32 warp tile at row offset arow, col offset bcol.
// kk/mi/ni order fixed -> per-output accumulation bit-identical across rounds.
__device__ __forceinline__ void mma_tile_ldsm(uint32_t aBase, uint32_t bBase,
                                              int arow, int bcol, int lane,
                                              float acc[4][4][4]) {
    int lr = lane & 15;
    int kadd = (lane >> 4) * 8;
#pragma unroll
    for (int kk = 0; kk < 32; kk += 16) {
        uint32_t a[4][4], b[4][2];
#pragma unroll
        for (int mi = 0; mi < 4; mi++) {
            uint32_t addr = aBase + (uint32_t)(((arow + mi*16 + lr)*TSTRIDE + kk + kadd) * 2);
            ldsm4(a[mi][0], a[mi][1], a[mi][2], a[mi][3], addr);
        }
#pragma unroll
        for (int np = 0; np < 2; np++) {
            uint32_t addr = bBase + (uint32_t)(((bcol + np*16 + lr)*TSTRIDE + kk + kadd) * 2);
            uint32_t r0, r1, r2, r3;
            ldsm4(r0, r1, r2, r3, addr);
            b[np*2][0]   = r0;
            b[np*2+1][0] = r1;
            b[np*2][1]   = r2;
            b[np*2+1][1] = r3;
        }
#pragma unroll
        for (int mi = 0; mi < 4; mi++)
#pragma unroll
            for (int ni = 0; ni < 4; ni++)
                mma16816(acc[mi][ni], a[mi], b[ni]);
    }
}

// ---------------- forward GEMM: pre[M,NH] = v[M,NV] @ (Whi|Wlo)^T + hb ----------------
// BM=128, BN=128, 256 threads, 4-stage cp.async pipeline, grid (128,2)=256 blocks, 2 CTA/SM
template<bool SAMPLE>
__global__ __launch_bounds__(256) void fgemm_kernel(
    const bf16* __restrict__ A, const bf16* __restrict__ Whi,
    const bf16* __restrict__ Wlo, const float* __restrict__ bias,
    float* __restrict__ C, bf16* __restrict__ H,
    uint32_t k0, uint32_t k1)
{
    extern __shared__ __align__(16) bf16 dsm[];
    int m0 = blockIdx.x * 128;
    int n0 = blockIdx.y * 128;
    int tid = threadIdx.x;
    int warp = tid >> 5, lane = tid & 31;
    int arow = (warp & 1) * 64;
    int bcol = (warp >> 1) * 32;
    uint32_t sbase = (uint32_t)__cvta_generic_to_shared(dsm);

    float acc[4][4][4];
#pragma unroll
    for (int mi = 0; mi < 4; mi++)
#pragma unroll
        for (int ni = 0; ni < 4; ni++)
#pragma unroll
            for (int j = 0; j < 4; j++) acc[mi][ni][j] = 0.0f;

    const int NIT = 64;
    // prologue: stages 0,1,2
#pragma unroll
    for (int jt = 0; jt < 3; jt++) {
        bf16* sA = dsm + jt*(2*STAGE_ELE);
        int k = (jt & 31) * 32;
        const bf16* Bp = (jt < 32) ? Whi : Wlo;
        load_tile128_t256(sA, A + (size_t)m0*NV + k, NV, tid);
        load_tile128_t256(sA + STAGE_ELE, Bp + (size_t)n0*NV + k, NV, tid);
        cpa_commit();
    }

    for (int it = 0; it < NIT; it++) {
        if (it == NIT-1) cpa_wait0();
        else if (it == NIT-2) cpa_wait1();
        else cpa_wait2();
        __syncthreads();
        if (it + 3 < NIT) {
            int jt = it + 3;
            int st = jt & 3;
            int k = (jt & 31) * 32;
            const bf16* Bp = (jt < 32) ? Whi : Wlo;
            bf16* sA = dsm + st*(2*STAGE_ELE);
            load_tile128_t256(sA, A + (size_t)m0*NV + k, NV, tid);
            load_tile128_t256(sA + STAGE_ELE, Bp + (size_t)n0*NV + k, NV, tid);
            cpa_commit();
        }
        int st = it & 3;
        uint32_t aB = sbase + st*STAGE_BYTES;
        mma_tile_ldsm(aB, aB + STAGE_ELE*2, arow, bcol, lane, acc);
    }

#pragma unroll
    for (int mi = 0; mi < 4; mi++) {
        int m = m0 + arow + mi*16 + (lane>>2);
#pragma unroll
        for (int ni = 0; ni < 4; ni++) {
            int n = n0 + bcol + ni*8 + 2*(lane&3);
            float2 b2 = *(const float2*)&bias[n];
            float p00 = acc[mi][ni][0] + b2.x;
            float p01 = acc[mi][ni][1] + b2.y;
            float p10 = acc[mi][ni][2] + b2.x;
            float p11 = acc[mi][ni][3] + b2.y;
            if (SAMPLE) {
                uint32_t e0 = (uint32_t)(m*NH + n);
                uint32_t e1 = (uint32_t)((m+8)*NH + n);
                __nv_bfloat162 h0, h1;
                h0.x = __float2bfloat16(tf_sample(k0, k1, e0,     p00));
                h0.y = __float2bfloat16(tf_sample(k0, k1, e0 + 1, p01));
                h1.x = __float2bfloat16(tf_sample(k0, k1, e1,     p10));
                h1.y = __float2bfloat16(tf_sample(k0, k1, e1 + 1, p11));
                *(__nv_bfloat162*)&H[(size_t)m*NH + n] = h0;
                *(__nv_bfloat162*)&H[(size_t)(m+8)*NH + n] = h1;
            } else {
                float2 r0 = { p00, p01 };
                float2 r1 = { p10, p11 };
                *(float2*)&C[(size_t)m*NH + n] = r0;
                *(float2*)&C[(size_t)(m+8)*NH + n] = r1;
            }
        }
    }
}

// ---------------- gw GEMM (split-K=16, 2x8x16=256 blocks, 3-stage) ----------------
__global__ __launch_bounds__(256) void gw_mma_kernel(
    const bf16* __restrict__ A0p, const bf16* __restrict__ A1p,
    const bf16* __restrict__ A2p, const bf16* __restrict__ A3p,
    const bf16* __restrict__ Bk, const bf16* __restrict__ B0,
    float* __restrict__ part)
{
    extern __shared__ __align__(16) bf16 dsm[];
    int m0 = blockIdx.x * 128;
    int n0 = blockIdx.y * 128;
    int ks = blockIdx.z;
    size_t kbase = (size_t)ks * (NB / GW_SPLITK);   // chunk 1024
    int tid = threadIdx.x;
    int warp = tid >> 5, lane = tid & 31;
    int arow = (warp & 1) * 64;
    int bcol = (warp >> 1) * 32;
    uint32_t sbase = (uint32_t)__cvta_generic_to_shared(dsm);

    const bf16* Ap[4] = { A0p, A1p, A2p, A3p };
    const bf16* Bp[4] = { Bk, Bk, B0, B0 };

    float acc[4][4][4];
#pragma unroll
    for (int mi = 0; mi < 4; mi++)
#pragma unroll
        for (int ni = 0; ni < 4; ni++)
#pragma unroll
            for (int j = 0; j < 4; j++) acc[mi][ni][j] = 0.0f;

    const int NIT = 128;   // 4 passes x 32 iters (chunk 1024 / 32)
#pragma unroll
    for (int jt = 0; jt < 2; jt++) {
        bf16* sA = dsm + jt*(2*STAGE_ELE);
        size_t k = kbase + (size_t)(jt & 31) * 32;
        load_tile128_t256(sA, Ap[0] + (size_t)m0*NB + k, NB, tid);
        load_tile128_t256(sA + STAGE_ELE, Bp[0] + (size_t)n0*NB + k, NB, tid);
        cpa_commit();
    }

    for (int it = 0; it < NIT; it++) {
        if (it == NIT-1) cpa_wait0(); else cpa_wait1();
        __syncthreads();
        if (it + 2 < NIT) {
            int jt = it + 2;
            int st = jt % 3;
            int p = jt >> 5;
            size_t k = kbase + (size_t)(jt & 31) * 32;
            bf16* sA = dsm + st*(2*STAGE_ELE);
            load_tile128_t256(sA, Ap[p] + (size_t)m0*NB + k, NB, tid);
            load_tile128_t256(sA + STAGE_ELE, Bp[p] + (size_t)n0*NB + k, NB, tid);
            cpa_commit();
        }
        int st = it % 3;
        uint32_t aB = sbase + st*STAGE_BYTES;
        mma_tile_ldsm(aB, aB + STAGE_ELE*2, arow, bcol, lane, acc);
    }

#pragma unroll
    for (int mi = 0; mi < 4; mi++) {
        int m = m0 + arow + mi*16 + (lane>>2);
#pragma unroll
        for (int ni = 0; ni < 4; ni++) {
            int n = n0 + bcol + ni*8 + 2*(lane&3);
            float2 r0 = { acc[mi][ni][0], acc[mi][ni][1] };
            float2 r1 = { acc[mi][ni][2], acc[mi][ni][3] };
            *(float2*)&part[(size_t)ks*GW_ELEMS + (size_t)m*NV + n] = r0;
            *(float2*)&part[(size_t)ks*GW_ELEMS + (size_t)(m+8)*NV + n] = r1;
        }
    }
}

// ---------------- fused sparse h @ W + vb -> sample visible -> bf16 v ----------------
// 2 warps per sample: warp half 0 -> cols [0,512), half 1 -> [512,1024)
__global__ __launch_bounds__(256) void spmm_sample_kernel(
    const bf16* __restrict__ h, const float* __restrict__ Wm,
    const float* __restrict__ vb, bf16* __restrict__ vout,
    uint32_t k0, uint32_t k1)
{
    int tid = threadIdx.x;
    int lane = tid & 31;
    int half = (tid >> 5) & 1;
    int sample = blockIdx.x * 4 + (tid >> 6);
    int cbase = half * 512 + lane;

    const bf16* hr = h + (size_t)sample * NH;
    float acc[16];
#pragma unroll
    for (int t = 0; t < 16; t++) acc[t] = vb[cbase + t*32];
#pragma unroll
    for (int g = 0; g < 8; g++) {
        float hv = __bfloat162float(hr[g*32 + lane]);
        unsigned mask = __ballot_sync(0xffffffffu, hv != 0.0f);
        while (mask) {
            int bit = __ffs(mask) - 1; mask &= mask - 1;
            const float* wr = Wm + (size_t)(g*32 + bit) * NV + cbase;
#pragma unroll
            for (int t = 0; t < 16; t++) acc[t] += wr[t*32];
        }
    }
    uint32_t ebase = (uint32_t)sample * NV + cbase;
    bf16* outp = vout + (size_t)sample * NV + cbase;
#pragma unroll
    for (int t = 0; t < 16; t++) {
        float s = tf_sample(k0, k1, ebase + t*32, acc[t]);
        outp[t*32] = __float2bfloat16(s);
    }
}

// ---------------- inv_norm ----------------
__global__ __launch_bounds__(256) void invn_kernel(
    const float* __restrict__ prek, const bf16* __restrict__ vk,
    const float* __restrict__ vb, float* __restrict__ invn)
{
    int warp = (blockIdx.x * blockDim.x + threadIdx.x) >> 5;
    int lane = threadIdx.x & 31;
    if (warp >= NB) return;
    float s = 0.0f;
    const float* pr = prek + (size_t)warp * NH;
#pragma unroll
    for (int t = 0; t < 8; t++) {
        float x = pr[t*32 + lane];
        s += fmaxf(x, 0.0f) + log1pf(expf(-fabsf(x)));
    }
    const bf16* vr = vk + (size_t)warp * NV;
#pragma unroll
    for (int t = 0; t < 32; t++)
        s = fmaf(__bfloat162float(vr[t*32 + lane]), vb[t*32 + lane], s);
#pragma unroll
    for (int o = 16; o > 0; o >>= 1) s += __shfl_xor_sync(0xffffffffu, s, o);
    if (lane == 0) invn[warp] = expf(-s) * (1.0f / (float)NB);
}

// ---------------- fused: a = sign*invn*sigmoid(pre), transpose + hi/lo split ----------
// z=0: preh -> +, akhi/aklo.  z=1: preh0 -> -, na0hi/na0lo
__global__ __launch_bounds__(256) void trans_a2_kernel(
    const float* __restrict__ srcA, const float* __restrict__ srcB,
    const float* __restrict__ invn,
    bf16* __restrict__ dhiA, bf16* __restrict__ dloA,
    bf16* __restrict__ dhiB, bf16* __restrict__ dloB)
{
    __shared__ float t[32][33];
    int b0 = blockIdx.x * 32, h0 = blockIdx.y * 32;
    const float* src = (blockIdx.z == 0) ? srcA : srcB;
    bf16* dhi = (blockIdx.z == 0) ? dhiA : dhiB;
    bf16* dlo = (blockIdx.z == 0) ? dloA : dloB;
    float sign = (blockIdx.z == 0) ? 1.0f : -1.0f;
    int tid = threadIdx.x;
#pragma unroll
    for (int i = 0; i < 4; i++) {
        int idx = tid + 256*i; int bl = idx >> 5, hl = idx & 31;
        float pre = src[(size_t)(b0+bl)*NH + h0 + hl];
        t[hl][bl] = invn[b0+bl] * sigmoid_f(pre);
    }
    __syncthreads();
#pragma unroll
    for (int i = 0; i < 4; i++) {
        int idx = tid + 256*i; int hl = idx >> 5, bl = idx & 31;
        float v = sign * t[hl][bl];
        bf16 hi = __float2bfloat16(v);
        float lo = v - __bfloat162float(hi);
        size_t o = (size_t)(h0+hl)*NB + b0 + bl;
        dhi[o] = hi; dlo[o] = __float2bfloat16(lo);
    }
}

// bf16 [NB,NV] -> bf16 [NV,NB] transpose, both states in one launch (z=0: vk, z=1: v0)
__global__ __launch_bounds__(256) void trans_vbf2_kernel(
    const bf16* __restrict__ srcA, bf16* __restrict__ dstA,
    const bf16* __restrict__ srcB, bf16* __restrict__ dstB)
{
    __shared__ uint16_t t[32][34];
    int b0 = blockIdx.x * 32, v0 = blockIdx.y * 32;
    const bf16* src = (blockIdx.z == 0) ? srcA : srcB;
    bf16* dst = (blockIdx.z == 0) ? dstA : dstB;
    int tid = threadIdx.x;
#pragma unroll
    for (int i = 0; i < 4; i++) {
        int idx = tid + 256*i; int bl = idx >> 5, vl = idx & 31;
        t[vl][bl] = ((const uint16_t*)src)[(size_t)(b0+bl)*NV + v0 + vl];
    }
    __syncthreads();
#pragma unroll
    for (int i = 0; i < 4; i++) {
        int idx = tid + 256*i; int vl = idx >> 5, bl = idx & 31;
        ((uint16_t*)dst)[(size_t)(v0+vl)*NB + b0 + bl] = t[vl][bl];
    }
}

// ---------------- fused W split + batch convert ----------------
__global__ __launch_bounds__(256) void prep_kernel(
    const float* __restrict__ W, bf16* __restrict__ whi, bf16* __restrict__ wlo,
    const float* __restrict__ batch, bf16* __restrict__ bbf)
{
    int i = blockIdx.x * 256 + threadIdx.x;
    if (i < NH*NV) {
        float w = W[i];
        bf16 hi = __float2bfloat16(w);
        whi[i] = hi;
        wlo[i] = __float2bfloat16(w - __bfloat162float(hi));
    }
    if (i < NB*NV) bbf[i] = __float2bfloat16(batch[i]);
}

// ---------------- g_vb / g_hb partials ----------------
__global__ __launch_bounds__(256) void vb_part_kernel(
    const bf16* __restrict__ vk, const bf16* __restrict__ v0,
    const float* __restrict__ invn, float* __restrict__ part)
{
    int v = blockIdx.x * 256 + threadIdx.x;
    int b0 = blockIdx.y * (NB / 32);
    float s = 0.0f;
    for (int b = b0; b < b0 + NB/32; b++) {
        float d = __bfloat162float(vk[(size_t)b*NV + v])
                - __bfloat162float(v0[(size_t)b*NV + v]);
        s = fmaf(invn[b], d, s);
    }
    part[blockIdx.y * NV + v] = s;
}

// hb partials from transposed hi/lo arrays
__global__ __launch_bounds__(256) void hb_part_kernel(
    const bf16* __restrict__ akhi, const bf16* __restrict__ aklo,
    const bf16* __restrict__ nahi, const bf16* __restrict__ nalo,
    float* __restrict__ part)
{
    int w = threadIdx.x >> 5, lane = threadIdx.x & 31;
    int h = blockIdx.x * 8 + w;
    int b0 = blockIdx.y * 512;
    size_t base = (size_t)h*NB + b0 + lane;
    float s = 0.0f;
#pragma unroll
    for (int j = 0; j < 16; j++) {
        size_t o = base + j*32;
        s += __bfloat162float(akhi[o]) + __bfloat162float(aklo[o])
           + __bfloat162float(nahi[o]) + __bfloat162float(nalo[o]);
    }
#pragma unroll
    for (int o = 16; o > 0; o >>= 1) s += __shfl_xor_sync(0xffffffffu, s, o);
    if (lane == 0) part[blockIdx.y * NH + h] = s;
}

// ---------------- finalize ----------------
__global__ __launch_bounds__(256) void finalize_kernel(
    const float* __restrict__ gw_part, const float* __restrict__ vb_part,
    const float* __restrict__ hb_part, float* __restrict__ out)
{
    int i = blockIdx.x * 256 + threadIdx.x;
    if (i < GW_ELEMS) {
        float s = 0.0f;
#pragma unroll
        for (int k = 0; k < GW_SPLITK; k++) s += gw_part[(size_t)k*GW_ELEMS + i];
        out[i] = s;
    } else if (i < OUT_HB_OFF) {
        int v = i - OUT_VB_OFF;
        float s = 0.0f;
#pragma unroll
        for (int k = 0; k < 32; k++) s += vb_part[k*NV + v];
        out[i] = s;
    } else if (i < OUT_TOTAL) {
        int h = i - OUT_HB_OFF;
        float s = 0.0f;
#pragma unroll
        for (int k = 0; k < 32; k++) s += hb_part[k*NH + h];
        out[i] = s;
    }
}

// ---------------- launch ----------------
extern "C" void kernel_launch(void* const* d_in, const int* in_sizes, int n_in,
                              void* d_out, int out_size)
{
    (void)in_sizes; (void)n_in; (void)out_size;
    const float* batch = (const float*)d_in[0];
    const float* W     = (const float*)d_in[1];
    const float* vb    = (const float*)d_in[2];
    const float* hb    = (const float*)d_in[3];
    float* out = (float*)d_out;

    float *ppreh, *ppreh0, *pinvn, *pgw, *pvbp, *phbp;
    bf16 *pvbf, *pbbf, *phbf, *pwhi, *pwlo, *pakhi, *paklo, *pna0hi, *pna0lo, *pvkT, *pv0T;
    cudaGetSymbolAddress((void**)&pvbf,   g_vbf);
    cudaGetSymbolAddress((void**)&pbbf,   g_batchbf);
    cudaGetSymbolAddress((void**)&phbf,   g_hbf);
    cudaGetSymbolAddress((void**)&ppreh,  g_preh);
    cudaGetSymbolAddress((void**)&ppreh0, g_preh0);
    cudaGetSymbolAddress((void**)&pinvn,  g_invn);
    cudaGetSymbolAddress((void**)&pwhi,   g_whi);
    cudaGetSymbolAddress((void**)&pwlo,   g_wlo);
    cudaGetSymbolAddress((void**)&pakhi,  g_akT_hi);
    cudaGetSymbolAddress((void**)&paklo,  g_akT_lo);
    cudaGetSymbolAddress((void**)&pna0hi, g_na0T_hi);
    cudaGetSymbolAddress((void**)&pna0lo, g_na0T_lo);
    cudaGetSymbolAddress((void**)&pvkT,   g_vkT);
    cudaGetSymbolAddress((void**)&pv0T,   g_v0T);
    cudaGetSymbolAddress((void**)&pgw,    g_gw_part);
    cudaGetSymbolAddress((void**)&pvbp,   g_vb_part);
    cudaGetSymbolAddress((void**)&phbp,   g_hb_part);

    cudaFuncSetAttribute(fgemm_kernel<true>,
        cudaFuncAttributeMaxDynamicSharedMemorySize, FG_SMEM_BYTES);
    cudaFuncSetAttribute(fgemm_kernel<false>,
        cudaFuncAttributeMaxDynamicSharedMemorySize, FG_SMEM_BYTES);
    cudaFuncSetAttribute(gw_mma_kernel,
        cudaFuncAttributeMaxDynamicSharedMemorySize, GW_SMEM_BYTES);

    // JAX partitionable split: key_m = threefry2x32((0,42), 0, m)
    uint32_t keys[16][2];
    for (int m = 0; m < 16; m++) {
        uint32_t o0, o1;
        threefry2x32(0u, 42u, 0u, (uint32_t)m, o0, o1);
        keys[m][0] = o0; keys[m][1] = o1;
    }

    const int totV = NB*NV;
    dim3 fgrid(NB/128, NH/128);   // (128, 2) = 256 blocks

    prep_kernel<<<(totV + 255)/256, 256>>>(W, pwhi, pwlo, batch, pbbf);

    for (int s = 0; s < KSTEPS; s++) {
        const bf16* Ain = (s == 0) ? pbbf : pvbf;
        fgemm_kernel<true><<<fgrid, 256, FG_SMEM_BYTES>>>(Ain, pwhi, pwlo, hb,
                                           (float*)nullptr, phbf,
                                           keys[2*s][0], keys[2*s][1]);
        spmm_sample_kernel<<<NB/4, 256>>>(phbf, W, vb, pvbf,
                                          keys[2*s+1][0], keys[2*s+1][1]);
    }

    fgemm_kernel<false><<<fgrid, 256, FG_SMEM_BYTES>>>(pvbf, pwhi, pwlo, hb,
                                        ppreh,  (bf16*)nullptr, 0u, 0u);
    fgemm_kernel<false><<<fgrid, 256, FG_SMEM_BYTES>>>(pbbf, pwhi, pwlo, hb,
                                        ppreh0, (bf16*)nullptr, 0u, 0u);
    invn_kernel<<<NB/8, 256>>>(ppreh, pvbf, vb, pinvn);

    trans_a2_kernel<<<dim3(NB/32, NH/32, 2), 256>>>(ppreh, ppreh0, pinvn,
                                                    pakhi, paklo, pna0hi, pna0lo);
    trans_vbf2_kernel<<<dim3(NB/32, NV/32, 2), 256>>>(pvbf, pvkT, pbbf, pv0T);

    gw_mma_kernel<<<dim3(NH/128, NV/128, GW_SPLITK), 256, GW_SMEM_BYTES>>>(
        pakhi, paklo, pna0hi, pna0lo, pvkT, pv0T, pgw);

    vb_part_kernel<<<dim3(NV/256, 32), 256>>>(pvbf, pbbf, pinvn, pvbp);
    hb_part_kernel<<<dim3(NH/8, 32), 256>>>(pakhi, paklo, pna0hi, pna0lo, phbp);
    finalize_kernel<<<(OUT_TOTAL + 255)/256, 256>>>(pgw, pvbp, phbp, out);
}

// round 17
// speedup vs baseline: 1.0641x; 1.0151x over previous
#include <cuda_runtime.h>
#include <cuda_bf16.h>
#include <cstdint>
#include <cstddef>

#define NB 16384
#define NV 1024
#define NH 256
#define KSTEPS 8
#define GW_ELEMS (NH*NV)          // 262144
#define OUT_VB_OFF GW_ELEMS
#define OUT_HB_OFF (GW_ELEMS+NV)
#define OUT_TOTAL (GW_ELEMS+NV+NH)
#define GW_SPLITK 16

typedef __nv_bfloat16 bf16;

// ---------------- static scratch ----------------
__device__ bf16  g_vbf[NB*NV];      // current visible state, bf16 (binary, exact)
__device__ bf16  g_batchbf[NB*NV];
__device__ bf16  g_hbf[NB*NH];      // hidden state, bf16 (binary, exact)
__device__ float g_preh[NB*NH];     // pre_k
__device__ float g_preh0[NB*NH];    // pre0
__device__ float g_invn[NB];
__device__ bf16  g_whi[NH*NV];
__device__ bf16  g_wlo[NH*NV];
__device__ bf16  g_akT_hi[NH*NB];
__device__ bf16  g_akT_lo[NH*NB];
__device__ bf16  g_na0T_hi[NH*NB];
__device__ bf16  g_na0T_lo[NH*NB];
__device__ bf16  g_vkT[NV*NB];
__device__ bf16  g_v0T[NV*NB];
__device__ float g_gw_part[GW_SPLITK*GW_ELEMS];
__device__ float g_vb_part[32*NV];
__device__ float g_hb_part[32*NH];

// ---------------- threefry2x32 (JAX partitionable) ----------------
__host__ __device__ __forceinline__ void threefry2x32(
    uint32_t k0, uint32_t k1, uint32_t c0, uint32_t c1,
    uint32_t& o0, uint32_t& o1)
{
    uint32_t k2 = k0 ^ k1 ^ 0x1BD11BDAu;
    uint32_t x0 = c0 + k0, x1 = c1 + k1;
#define TF_R(r) { x0 += x1; x1 = (x1 << (r)) | (x1 >> (32 - (r))); x1 ^= x0; }
    TF_R(13) TF_R(15) TF_R(26) TF_R(6)
    x0 += k1; x1 += k2 + 1u;
    TF_R(17) TF_R(29) TF_R(16) TF_R(24)
    x0 += k2; x1 += k0 + 2u;
    TF_R(13) TF_R(15) TF_R(26) TF_R(6)
    x0 += k0; x1 += k1 + 3u;
    TF_R(17) TF_R(29) TF_R(16) TF_R(24)
    x0 += k1; x1 += k2 + 4u;
    TF_R(13) TF_R(15) TF_R(26) TF_R(6)
    x0 += k2; x1 += k0 + 5u;
#undef TF_R
    o0 = x0; o1 = x1;
}

__device__ __forceinline__ float tf_uniform(uint32_t bits) {
    return __uint_as_float((bits >> 9) | 0x3f800000u) - 1.0f;
}
__device__ __forceinline__ float sigmoid_f(float x) {
    return 1.0f / (1.0f + expf(-x));
}
__device__ __forceinline__ float tf_sample(uint32_t k0, uint32_t k1, uint32_t e, float pre) {
    uint32_t o0, o1;
    threefry2x32(k0, k1, 0u, e, o0, o1);
    return (tf_uniform(o0 ^ o1) < sigmoid_f(pre)) ? 1.0f : 0.0f;
}

// ---------------- cp.async / ldmatrix / mma helpers ----------------
__device__ __forceinline__ void cpa16(void* s, const void* g) {
    uint32_t sa = (uint32_t)__cvta_generic_to_shared(s);
    asm volatile("cp.async.ca.shared.global [%0], [%1], 16;\n" :: "r"(sa), "l"(g));
}
__device__ __forceinline__ void cpa_commit() {
    asm volatile("cp.async.commit_group;\n" ::);
}
__device__ __forceinline__ void cpa_wait1() {
    asm volatile("cp.async.wait_group 1;\n" ::);
}
__device__ __forceinline__ void cpa_wait0() {
    asm volatile("cp.async.wait_group 0;\n" ::);
}
__device__ __forceinline__ void ldsm4(uint32_t& r0, uint32_t& r1, uint32_t& r2, uint32_t& r3,
                                      uint32_t addr) {
    asm volatile("ldmatrix.sync.aligned.m8n8.x4.shared.b16 {%0,%1,%2,%3}, [%4];\n"
                 : "=r"(r0), "=r"(r1), "=r"(r2), "=r"(r3) : "r"(addr));
}
__device__ __forceinline__ void mma16816(float* c, const uint32_t* a, const uint32_t* b) {
    asm volatile(
        "mma.sync.aligned.m16n8k16.row.col.f32.bf16.bf16.f32 "
        "{%0,%1,%2,%3}, {%4,%5,%6,%7}, {%8,%9}, {%0,%1,%2,%3};\n"
        : "+f"(c[0]), "+f"(c[1]), "+f"(c[2]), "+f"(c[3])
        : "r"(a[0]), "r"(a[1]), "r"(a[2]), "r"(a[3]), "r"(b[0]), "r"(b[1]));
}

// SMEM tile row stride: 32 bf16 payload, stride 40 bf16 (80B: 16B-aligned, LDSM conflict-free)
#define TSTRIDE 40
#define STAGE_ELE (128*TSTRIDE)
#define STAGE_BYTES (2*STAGE_ELE*2)        // 20480
#define GEMM_SMEM_BYTES (3*STAGE_BYTES)    // 61440 (3-stage)

// 128-row tile loader, 256 threads (2 chunks each)
__device__ __forceinline__ void load_tile128_t256(bf16* s, const bf16* g, size_t ldg, int tid) {
#pragma unroll
    for (int i = 0; i < 2; i++) {
        int c = tid + 256*i;
        int row = c >> 2, w = c & 3;
        cpa16(s + row*TSTRIDE + w*8, g + (size_t)row*ldg + w*8);
    }
}

// ldmatrix-based compute of one (64x128)x32 warp tile at row offset arow, col offset bcol.
// kk/mi/ni order fixed -> per-output accumulation bit-identical across rounds.
__device__ __forceinline__ void mma_tile_ldsm(uint32_t aBase, uint32_t bBase,
                                              int arow, int bcol, int lane,
                                              float acc[4][4][4]) {
    int lr = lane & 15;
    int kadd = (lane >> 4) * 8;
#pragma unroll
    for (int kk = 0; kk < 32; kk += 16) {
        uint32_t a[4][4], b[4][2];
#pragma unroll
        for (int mi = 0; mi < 4; mi++) {
            uint32_t addr = aBase + (uint32_t)(((arow + mi*16 + lr)*TSTRIDE + kk + kadd) * 2);
            ldsm4(a[mi][0], a[mi][1], a[mi][2], a[mi][3], addr);
        }
#pragma unroll
        for (int np = 0; np < 2; np++) {
            uint32_t addr = bBase + (uint32_t)(((bcol + np*16 + lr)*TSTRIDE + kk + kadd) * 2);
            uint32_t r0, r1, r2, r3;
            ldsm4(r0, r1, r2, r3, addr);
            b[np*2][0]   = r0;
            b[np*2+1][0] = r1;
            b[np*2][1]   = r2;
            b[np*2+1][1] = r3;
        }
#pragma unroll
        for (int mi = 0; mi < 4; mi++)
#pragma unroll
            for (int ni = 0; ni < 4; ni++)
                mma16816(acc[mi][ni], a[mi], b[ni]);
    }
}

// ---------------- forward GEMM: pre[M,NH] = v[M,NV] @ (Whi|Wlo)^T + hb ----------------
// BM=128, BN=128, 256 threads, 3-stage cp.async pipeline (R10 config), grid (128,2)
template<bool SAMPLE>
__global__ __launch_bounds__(256) void fgemm_kernel(
    const bf16* __restrict__ A, const bf16* __restrict__ Whi,
    const bf16* __restrict__ Wlo, const float* __restrict__ bias,
    float* __restrict__ C, bf16* __restrict__ H,
    uint32_t k0, uint32_t k1)
{
    extern __shared__ __align__(16) bf16 dsm[];
    int m0 = blockIdx.x * 128;
    int n0 = blockIdx.y * 128;
    int tid = threadIdx.x;
    int warp = tid >> 5, lane = tid & 31;
    int arow = (warp & 1) * 64;
    int bcol = (warp >> 1) * 32;
    uint32_t sbase = (uint32_t)__cvta_generic_to_shared(dsm);

    float acc[4][4][4];
#pragma unroll
    for (int mi = 0; mi < 4; mi++)
#pragma unroll
        for (int ni = 0; ni < 4; ni++)
#pragma unroll
            for (int j = 0; j < 4; j++) acc[mi][ni][j] = 0.0f;

    const int NIT = 64;
    // prologue: stages 0,1
#pragma unroll
    for (int jt = 0; jt < 2; jt++) {
        bf16* sA = dsm + jt*(2*STAGE_ELE);
        int k = (jt & 31) * 32;
        load_tile128_t256(sA, A + (size_t)m0*NV + k, NV, tid);
        load_tile128_t256(sA + STAGE_ELE, Whi + (size_t)n0*NV + k, NV, tid);
        cpa_commit();
    }

    for (int it = 0; it < NIT; it++) {
        if (it == NIT-1) cpa_wait0(); else cpa_wait1();
        __syncthreads();
        if (it + 2 < NIT) {
            int jt = it + 2;
            int st = jt % 3;
            int k = (jt & 31) * 32;
            const bf16* Bp = (jt < 32) ? Whi : Wlo;
            bf16* sA = dsm + st*(2*STAGE_ELE);
            load_tile128_t256(sA, A + (size_t)m0*NV + k, NV, tid);
            load_tile128_t256(sA + STAGE_ELE, Bp + (size_t)n0*NV + k, NV, tid);
            cpa_commit();
        }
        int st = it % 3;
        uint32_t aB = sbase + st*STAGE_BYTES;
        mma_tile_ldsm(aB, aB + STAGE_ELE*2, arow, bcol, lane, acc);
    }

#pragma unroll
    for (int mi = 0; mi < 4; mi++) {
        int m = m0 + arow + mi*16 + (lane>>2);
#pragma unroll
        for (int ni = 0; ni < 4; ni++) {
            int n = n0 + bcol + ni*8 + 2*(lane&3);
            float2 b2 = *(const float2*)&bias[n];
            float p00 = acc[mi][ni][0] + b2.x;
            float p01 = acc[mi][ni][1] + b2.y;
            float p10 = acc[mi][ni][2] + b2.x;
            float p11 = acc[mi][ni][3] + b2.y;
            if (SAMPLE) {
                uint32_t e0 = (uint32_t)(m*NH + n);
                uint32_t e1 = (uint32_t)((m+8)*NH + n);
                __nv_bfloat162 h0, h1;
                h0.x = __float2bfloat16(tf_sample(k0, k1, e0,     p00));
                h0.y = __float2bfloat16(tf_sample(k0, k1, e0 + 1, p01));
                h1.x = __float2bfloat16(tf_sample(k0, k1, e1,     p10));
                h1.y = __float2bfloat16(tf_sample(k0, k1, e1 + 1, p11));
                *(__nv_bfloat162*)&H[(size_t)m*NH + n] = h0;
                *(__nv_bfloat162*)&H[(size_t)(m+8)*NH + n] = h1;
            } else {
                float2 r0 = { p00, p01 };
                float2 r1 = { p10, p11 };
                *(float2*)&C[(size_t)m*NH + n] = r0;
                *(float2*)&C[(size_t)(m+8)*NH + n] = r1;
            }
        }
    }
}

// ---------------- gw GEMM (split-K=16, 2x8x16=256 blocks, 3-stage) ----------------
__global__ __launch_bounds__(256) void gw_mma_kernel(
    const bf16* __restrict__ A0p, const bf16* __restrict__ A1p,
    const bf16* __restrict__ A2p, const bf16* __restrict__ A3p,
    const bf16* __restrict__ Bk, const bf16* __restrict__ B0,
    float* __restrict__ part)
{
    extern __shared__ __align__(16) bf16 dsm[];
    int m0 = blockIdx.x * 128;
    int n0 = blockIdx.y * 128;
    int ks = blockIdx.z;
    size_t kbase = (size_t)ks * (NB / GW_SPLITK);   // chunk 1024
    int tid = threadIdx.x;
    int warp = tid >> 5, lane = tid & 31;
    int arow = (warp & 1) * 64;
    int bcol = (warp >> 1) * 32;
    uint32_t sbase = (uint32_t)__cvta_generic_to_shared(dsm);

    const bf16* Ap[4] = { A0p, A1p, A2p, A3p };
    const bf16* Bp[4] = { Bk, Bk, B0, B0 };

    float acc[4][4][4];
#pragma unroll
    for (int mi = 0; mi < 4; mi++)
#pragma unroll
        for (int ni = 0; ni < 4; ni++)
#pragma unroll
            for (int j = 0; j < 4; j++) acc[mi][ni][j] = 0.0f;

    const int NIT = 128;   // 4 passes x 32 iters
#pragma unroll
    for (int jt = 0; jt < 2; jt++) {
        bf16* sA = dsm + jt*(2*STAGE_ELE);
        size_t k = kbase + (size_t)(jt & 31) * 32;
        load_tile128_t256(sA, Ap[0] + (size_t)m0*NB + k, NB, tid);
        load_tile128_t256(sA + STAGE_ELE, Bp[0] + (size_t)n0*NB + k, NB, tid);
        cpa_commit();
    }

    for (int it = 0; it < NIT; it++) {
        if (it == NIT-1) cpa_wait0(); else cpa_wait1();
        __syncthreads();
        if (it + 2 < NIT) {
            int jt = it + 2;
            int st = jt % 3;
            int p = jt >> 5;
            size_t k = kbase + (size_t)(jt & 31) * 32;
            bf16* sA = dsm + st*(2*STAGE_ELE);
            load_tile128_t256(sA, Ap[p] + (size_t)m0*NB + k, NB, tid);
            load_tile128_t256(sA + STAGE_ELE, Bp[p] + (size_t)n0*NB + k, NB, tid);
            cpa_commit();
        }
        int st = it % 3;
        uint32_t aB = sbase + st*STAGE_BYTES;
        mma_tile_ldsm(aB, aB + STAGE_ELE*2, arow, bcol, lane, acc);
    }

#pragma unroll
    for (int mi = 0; mi < 4; mi++) {
        int m = m0 + arow + mi*16 + (lane>>2);
#pragma unroll
        for (int ni = 0; ni < 4; ni++) {
            int n = n0 + bcol + ni*8 + 2*(lane&3);
            float2 r0 = { acc[mi][ni][0], acc[mi][ni][1] };
            float2 r1 = { acc[mi][ni][2], acc[mi][ni][3] };
            *(float2*)&part[(size_t)ks*GW_ELEMS + (size_t)m*NV + n] = r0;
            *(float2*)&part[(size_t)ks*GW_ELEMS + (size_t)(m+8)*NV + n] = r1;
        }
    }
}

// ---------------- fused sparse h @ W + vb -> sample visible -> bf16 v ----------------
// 2 warps per sample: warp half 0 -> cols [0,512), half 1 -> [512,1024)
__global__ __launch_bounds__(256) void spmm_sample_kernel(
    const bf16* __restrict__ h, const float* __restrict__ Wm,
    const float* __restrict__ vb, bf16* __restrict__ vout,
    uint32_t k0, uint32_t k1)
{
    int tid = threadIdx.x;
    int lane = tid & 31;
    int half = (tid >> 5) & 1;
    int sample = blockIdx.x * 4 + (tid >> 6);
    int cbase = half * 512 + lane;

    const bf16* hr = h + (size_t)sample * NH;
    float acc[16];
#pragma unroll
    for (int t = 0; t < 16; t++) acc[t] = vb[cbase + t*32];
#pragma unroll
    for (int g = 0; g < 8; g++) {
        float hv = __bfloat162float(hr[g*32 + lane]);
        unsigned mask = __ballot_sync(0xffffffffu, hv != 0.0f);
        while (mask) {
            int bit = __ffs(mask) - 1; mask &= mask - 1;
            const float* wr = Wm + (size_t)(g*32 + bit) * NV + cbase;
#pragma unroll
            for (int t = 0; t < 16; t++) acc[t] += wr[t*32];
        }
    }
    uint32_t ebase = (uint32_t)sample * NV + cbase;
    bf16* outp = vout + (size_t)sample * NV + cbase;
#pragma unroll
    for (int t = 0; t < 16; t++) {
        float s = tf_sample(k0, k1, ebase + t*32, acc[t]);
        outp[t*32] = __float2bfloat16(s);
    }
}

// ---------------- inv_norm ----------------
__global__ __launch_bounds__(256) void invn_kernel(
    const float* __restrict__ prek, const bf16* __restrict__ vk,
    const float* __restrict__ vb, float* __restrict__ invn)
{
    int warp = (blockIdx.x * blockDim.x + threadIdx.x) >> 5;
    int lane = threadIdx.x & 31;
    if (warp >= NB) return;
    float s = 0.0f;
    const float* pr = prek + (size_t)warp * NH;
#pragma unroll
    for (int t = 0; t < 8; t++) {
        float x = pr[t*32 + lane];
        s += fmaxf(x, 0.0f) + log1pf(expf(-fabsf(x)));
    }
    const bf16* vr = vk + (size_t)warp * NV;
#pragma unroll
    for (int t = 0; t < 32; t++)
        s = fmaf(__bfloat162float(vr[t*32 + lane]), vb[t*32 + lane], s);
#pragma unroll
    for (int o = 16; o > 0; o >>= 1) s += __shfl_xor_sync(0xffffffffu, s, o);
    if (lane == 0) invn[warp] = expf(-s) * (1.0f / (float)NB);
}

// ---------------- fused: a = sign*invn*sigmoid(pre), transpose + hi/lo split ----------
// z=0: preh -> +, akhi/aklo.  z=1: preh0 -> -, na0hi/na0lo
__global__ __launch_bounds__(256) void trans_a2_kernel(
    const float* __restrict__ srcA, const float* __restrict__ srcB,
    const float* __restrict__ invn,
    bf16* __restrict__ dhiA, bf16* __restrict__ dloA,
    bf16* __restrict__ dhiB, bf16* __restrict__ dloB)
{
    __shared__ float t[32][33];
    int b0 = blockIdx.x * 32, h0 = blockIdx.y * 32;
    const float* src = (blockIdx.z == 0) ? srcA : srcB;
    bf16* dhi = (blockIdx.z == 0) ? dhiA : dhiB;
    bf16* dlo = (blockIdx.z == 0) ? dloA : dloB;
    float sign = (blockIdx.z == 0) ? 1.0f : -1.0f;
    int tid = threadIdx.x;
#pragma unroll
    for (int i = 0; i < 4; i++) {
        int idx = tid + 256*i; int bl = idx >> 5, hl = idx & 31;
        float pre = src[(size_t)(b0+bl)*NH + h0 + hl];
        t[hl][bl] = invn[b0+bl] * sigmoid_f(pre);
    }
    __syncthreads();
#pragma unroll
    for (int i = 0; i < 4; i++) {
        int idx = tid + 256*i; int hl = idx >> 5, bl = idx & 31;
        float v = sign * t[hl][bl];
        bf16 hi = __float2bfloat16(v);
        float lo = v - __bfloat162float(hi);
        size_t o = (size_t)(h0+hl)*NB + b0 + bl;
        dhi[o] = hi; dlo[o] = __float2bfloat16(lo);
    }
}

// bf16 [NB,NV] -> bf16 [NV,NB] transpose, both states in one launch
__global__ __launch_bounds__(256) void trans_vbf2_kernel(
    const bf16* __restrict__ srcA, bf16* __restrict__ dstA,
    const bf16* __restrict__ srcB, bf16* __restrict__ dstB)
{
    __shared__ uint16_t t[32][34];
    int b0 = blockIdx.x * 32, v0 = blockIdx.y * 32;
    const bf16* src = (blockIdx.z == 0) ? srcA : srcB;
    bf16* dst = (blockIdx.z == 0) ? dstA : dstB;
    int tid = threadIdx.x;
#pragma unroll
    for (int i = 0; i < 4; i++) {
        int idx = tid + 256*i; int bl = idx >> 5, vl = idx & 31;
        t[vl][bl] = ((const uint16_t*)src)[(size_t)(b0+bl)*NV + v0 + vl];
    }
    __syncthreads();
#pragma unroll
    for (int i = 0; i < 4; i++) {
        int idx = tid + 256*i; int vl = idx >> 5, bl = idx & 31;
        ((uint16_t*)dst)[(size_t)(v0+vl)*NB + b0 + bl] = t[vl][bl];
    }
}

// ---------------- fused W split + batch convert ----------------
__global__ __launch_bounds__(256) void prep_kernel(
    const float* __restrict__ W, bf16* __restrict__ whi, bf16* __restrict__ wlo,
    const float* __restrict__ batch, bf16* __restrict__ bbf)
{
    int i = blockIdx.x * 256 + threadIdx.x;
    if (i < NH*NV) {
        float w = W[i];
        bf16 hi = __float2bfloat16(w);
        whi[i] = hi;
        wlo[i] = __float2bfloat16(w - __bfloat162float(hi));
    }
    if (i < NB*NV) bbf[i] = __float2bfloat16(batch[i]);
}

// ---------------- g_vb / g_hb partials ----------------
__global__ __launch_bounds__(256) void vb_part_kernel(
    const bf16* __restrict__ vk, const bf16* __restrict__ v0,
    const float* __restrict__ invn, float* __restrict__ part)
{
    int v = blockIdx.x * 256 + threadIdx.x;
    int b0 = blockIdx.y * (NB / 32);
    float s = 0.0f;
    for (int b = b0; b < b0 + NB/32; b++) {
        float d = __bfloat162float(vk[(size_t)b*NV + v])
                - __bfloat162float(v0[(size_t)b*NV + v]);
        s = fmaf(invn[b], d, s);
    }
    part[blockIdx.y * NV + v] = s;
}

// hb partials from transposed hi/lo arrays
__global__ __launch_bounds__(256) void hb_part_kernel(
    const bf16* __restrict__ akhi, const bf16* __restrict__ aklo,
    const bf16* __restrict__ nahi, const bf16* __restrict__ nalo,
    float* __restrict__ part)
{
    int w = threadIdx.x >> 5, lane = threadIdx.x & 31;
    int h = blockIdx.x * 8 + w;
    int b0 = blockIdx.y * 512;
    size_t base = (size_t)h*NB + b0 + lane;
    float s = 0.0f;
#pragma unroll
    for (int j = 0; j < 16; j++) {
        size_t o = base + j*32;
        s += __bfloat162float(akhi[o]) + __bfloat162float(aklo[o])
           + __bfloat162float(nahi[o]) + __bfloat162float(nalo[o]);
    }
#pragma unroll
    for (int o = 16; o > 0; o >>= 1) s += __shfl_xor_sync(0xffffffffu, s, o);
    if (lane == 0) part[blockIdx.y * NH + h] = s;
}

// ---------------- finalize ----------------
__global__ __launch_bounds__(256) void finalize_kernel(
    const float* __restrict__ gw_part, const float* __restrict__ vb_part,
    const float* __restrict__ hb_part, float* __restrict__ out)
{
    int i = blockIdx.x * 256 + threadIdx.x;
    if (i < GW_ELEMS) {
        float s = 0.0f;
#pragma unroll
        for (int k = 0; k < GW_SPLITK; k++) s += gw_part[(size_t)k*GW_ELEMS + i];
        out[i] = s;
    } else if (i < OUT_HB_OFF) {
        int v = i - OUT_VB_OFF;
        float s = 0.0f;
#pragma unroll
        for (int k = 0; k < 32; k++) s += vb_part[k*NV + v];
        out[i] = s;
    } else if (i < OUT_TOTAL) {
        int h = i - OUT_HB_OFF;
        float s = 0.0f;
#pragma unroll
        for (int k = 0; k < 32; k++) s += hb_part[k*NH + h];
        out[i] = s;
    }
}

// ---------------- launch ----------------
extern "C" void kernel_launch(void* const* d_in, const int* in_sizes, int n_in,
                              void* d_out, int out_size)
{
    (void)in_sizes; (void)n_in; (void)out_size;
    const float* batch = (const float*)d_in[0];
    const float* W     = (const float*)d_in[1];
    const float* vb    = (const float*)d_in[2];
    const float* hb    = (const float*)d_in[3];
    float* out = (float*)d_out;

    float *ppreh, *ppreh0, *pinvn, *pgw, *pvbp, *phbp;
    bf16 *pvbf, *pbbf, *phbf, *pwhi, *pwlo, *pakhi, *paklo, *pna0hi, *pna0lo, *pvkT, *pv0T;
    cudaGetSymbolAddress((void**)&pvbf,   g_vbf);
    cudaGetSymbolAddress((void**)&pbbf,   g_batchbf);
    cudaGetSymbolAddress((void**)&phbf,   g_hbf);
    cudaGetSymbolAddress((void**)&ppreh,  g_preh);
    cudaGetSymbolAddress((void**)&ppreh0, g_preh0);
    cudaGetSymbolAddress((void**)&pinvn,  g_invn);
    cudaGetSymbolAddress((void**)&pwhi,   g_whi);
    cudaGetSymbolAddress((void**)&pwlo,   g_wlo);
    cudaGetSymbolAddress((void**)&pakhi,  g_akT_hi);
    cudaGetSymbolAddress((void**)&paklo,  g_akT_lo);
    cudaGetSymbolAddress((void**)&pna0hi, g_na0T_hi);
    cudaGetSymbolAddress((void**)&pna0lo, g_na0T_lo);
    cudaGetSymbolAddress((void**)&pvkT,   g_vkT);
    cudaGetSymbolAddress((void**)&pv0T,   g_v0T);
    cudaGetSymbolAddress((void**)&pgw,    g_gw_part);
    cudaGetSymbolAddress((void**)&pvbp,   g_vb_part);
    cudaGetSymbolAddress((void**)&phbp,   g_hb_part);

    cudaFuncSetAttribute(fgemm_kernel<true>,
        cudaFuncAttributeMaxDynamicSharedMemorySize, GEMM_SMEM_BYTES);
    cudaFuncSetAttribute(fgemm_kernel<false>,
        cudaFuncAttributeMaxDynamicSharedMemorySize, GEMM_SMEM_BYTES);
    cudaFuncSetAttribute(gw_mma_kernel,
        cudaFuncAttributeMaxDynamicSharedMemorySize, GEMM_SMEM_BYTES);

    // JAX partitionable split: key_m = threefry2x32((0,42), 0, m)
    uint32_t keys[16][2];
    for (int m = 0; m < 16; m++) {
        uint32_t o0, o1;
        threefry2x32(0u, 42u, 0u, (uint32_t)m, o0, o1);
        keys[m][0] = o0; keys[m][1] = o1;
    }

    const int totV = NB*NV;
    dim3 fgrid(NB/128, NH/128);   // (128, 2) = 256 blocks

    prep_kernel<<<(totV + 255)/256, 256>>>(W, pwhi, pwlo, batch, pbbf);

    for (int s = 0; s < KSTEPS; s++) {
        const bf16* Ain = (s == 0) ? pbbf : pvbf;
        fgemm_kernel<true><<<fgrid, 256, GEMM_SMEM_BYTES>>>(Ain, pwhi, pwlo, hb,
                                           (float*)nullptr, phbf,
                                           keys[2*s][0], keys[2*s][1]);
        spmm_sample_kernel<<<NB/4, 256>>>(phbf, W, vb, pvbf,
                                          keys[2*s+1][0], keys[2*s+1][1]);
    }

    fgemm_kernel<false><<<fgrid, 256, GEMM_SMEM_BYTES>>>(pvbf, pwhi, pwlo, hb,
                                        ppreh,  (bf16*)nullptr, 0u, 0u);
    fgemm_kernel<false><<<fgrid, 256, GEMM_SMEM_BYTES>>>(pbbf, pwhi, pwlo, hb,
                                        ppreh0, (bf16*)nullptr, 0u, 0u);
    invn_kernel<<<NB/8, 256>>>(ppreh, pvbf, vb, pinvn);

    trans_a2_kernel<<<dim3(NB/32, NH/32, 2), 256>>>(ppreh, ppreh0, pinvn,
                                                    pakhi, paklo, pna0hi, pna0lo);
    trans_vbf2_kernel<<<dim3(NB/32, NV/32, 2), 256>>>(pvbf, pvkT, pbbf, pv0T);

    gw_mma_kernel<<<dim3(NH/128, NV/128, GW_SPLITK), 256, GEMM_SMEM_BYTES>>>(
        pakhi, paklo, pna0hi, pna0lo, pvkT, pv0T, pgw);

    vb_part_kernel<<<dim3(NV/256, 32), 256>>>(pvbf, pbbf, pinvn, pvbp);
    hb_part_kernel<<<dim3(NH/8, 32), 256>>>(pakhi, paklo, pna0hi, pna0lo, phbp);
    finalize_kernel<<<(OUT_TOTAL + 255)/256, 256>>>(pgw, pvbp, phbp, out);
}